// round 13
// baseline (speedup 1.0000x reference)
#include <cuda_runtime.h>
#include <cuda_bf16.h>
#include <cstdint>

// Problem constants (fixed by the reference)
#define PN   64      // batch
#define PL   2048    // sequence length
#define PC   256     // timestep channels
#define PCQ  (PC / 4)       // 64 channel-quads
#define PDEM 10
#define PCO  276     // output channels = 256 + 20
#define PCOQ (PCO / 4)      // 69 output quads
#define SSEG 16      // segments along L
#define SEGL (PL / SSEG)    // 128
#define SUBL 32      // sub-segment rows (one row-phase)
#define NSUB 4       // sub-segments per segment
#define PSEG 4       // segments per pipeline phase (4 phases total)

// Scratch (allocation-free __device__ globals, float4-aligned)
__device__ float4 g_sub_sum[PN * SSEG * NSUB * PCQ];  // [n][s*4+p][q]
__device__ float4 g_sub_cnt[PN * SSEG * NSUB * PCQ];
__device__ float4 g_seg_sum[PN * SSEG * PCQ];         // [n][s][q]
__device__ float4 g_seg_cnt[PN * SSEG * PCQ];

// ---------------------------------------------------------------------------
// Combined pipelined kernel. Grid (2*PSEG, PN), 256 threads.
//   blockIdx.x <  PSEG : AGG role, segment  s = agg_ph*PSEG + blockIdx.x
//   blockIdx.x >= PSEG : EMIT role, segment s = emit_ph*PSEG + (blockIdx.x-PSEG)
// Roles are independent (emit reads aggregates produced in PREVIOUS launches);
// the kernel boundary is the only synchronization. A negative phase id turns
// the role off for that launch (uniform early exit).
//
// AGG: thread t (p=t>>6, q=t&63) aggregates rows [s*128+32p, +32) (float4,
//      L2-allocating loads -> chunk stays hot for next launch's emit),
//      writes sub- and segment aggregates; also computes the dem MLP and
//      writes the 20 constant dem output channels for its segment.
// EMIT: two-level lookback (<=15 seg + <=3 sub aggregates, L2-hot), then
//      scans its 32 rows: LDG.128 -> FADDs -> MUFU rcp -> STG.128 streaming.
// ---------------------------------------------------------------------------
__global__ void __launch_bounds__(256)
pipe_kernel(const float4* __restrict__ ts4,
            const float* __restrict__ dem,
            const float* __restrict__ W1,
            const float* __restrict__ b1,
            const float* __restrict__ W2,
            const float* __restrict__ b2,
            float4* __restrict__ out4,
            int agg_ph, int emit_ph) {
    const int n = blockIdx.y, t = threadIdx.x;
    const int p = t >> 6, q = t & 63;
    const bool is_agg = (blockIdx.x < PSEG);

    if (is_agg) {
        // ---------------- AGG role ----------------
        if (agg_ph < 0) return;
        const int s = agg_ph * PSEG + blockIdx.x;

        __shared__ float  s_sum[NSUB][PC];
        __shared__ float  s_cnt[NSUB][PC];
        __shared__ float  s_h[40];
        __shared__ float4 s_dem4[5];

        const float4* base =
            ts4 + ((size_t)(n * PL + s * SEGL + SUBL * p)) * PCQ + q;

        float4 a = make_float4(0.f, 0.f, 0.f, 0.f);
        float4 c = make_float4(0.f, 0.f, 0.f, 0.f);
        #pragma unroll 8
        for (int i = SUBL - 1; i >= 0; i--) {
            float4 v = __ldcg(&base[(size_t)i * PCQ]);
            a.x += v.x; a.y += v.y; a.z += v.z; a.w += v.w;
            c.x += (v.x != 0.f) ? 1.f : 0.f;
            c.y += (v.y != 0.f) ? 1.f : 0.f;
            c.z += (v.z != 0.f) ? 1.f : 0.f;
            c.w += (v.w != 0.f) ? 1.f : 0.f;
        }

        const int sub_idx = ((n * SSEG + s) * NSUB + p) * PCQ + q;
        g_sub_sum[sub_idx] = a;
        g_sub_cnt[sub_idx] = c;

        if (t < 40) {
            float acc = b1[t];
            #pragma unroll
            for (int k = 0; k < PDEM; k++)
                acc = fmaf(dem[n * PDEM + k], W1[k * 40 + t], acc);
            s_h[t] = fmaxf(acc, 0.0f);
        }

        s_sum[p][4 * q + 0] = a.x; s_sum[p][4 * q + 1] = a.y;
        s_sum[p][4 * q + 2] = a.z; s_sum[p][4 * q + 3] = a.w;
        s_cnt[p][4 * q + 0] = c.x; s_cnt[p][4 * q + 1] = c.y;
        s_cnt[p][4 * q + 2] = c.z; s_cnt[p][4 * q + 3] = c.w;
        __syncthreads();

        if (t < 20) {
            float acc = b2[t];
            #pragma unroll
            for (int k = 0; k < 40; k++) acc = fmaf(s_h[k], W2[k * 20 + t], acc);
            ((float*)s_dem4)[t] = fmaxf(acc, 0.0f);
        }

        float S = ((s_sum[0][t] + s_sum[1][t]) + s_sum[2][t]) + s_sum[3][t];
        float C = ((s_cnt[0][t] + s_cnt[1][t]) + s_cnt[2][t]) + s_cnt[3][t];
        const int seg_base = (n * SSEG + s) * PCQ;
        ((float*)&g_seg_sum[seg_base])[t] = S;
        ((float*)&g_seg_cnt[seg_base])[t] = C;
        __syncthreads();

        float4* obseg = out4 + ((size_t)(n * PL + s * SEGL)) * PCOQ;
        #pragma unroll
        for (int j = t; j < SEGL * 5; j += 256) {
            int row = j / 5;
            int cc  = j - row * 5;
            __stcs(&obseg[(size_t)row * PCOQ + PCQ + cc], s_dem4[cc]);
        }
    } else {
        // ---------------- EMIT role ----------------
        if (emit_ph < 0) return;
        const int s = emit_ph * PSEG + (blockIdx.x - PSEG);

        float4 ps = make_float4(0.f, 0.f, 0.f, 0.f);
        float4 pc = make_float4(0.f, 0.f, 0.f, 0.f);
        #pragma unroll
        for (int j = 0; j < SSEG - 1; j++) {
            if (j < s) {
                float4 a = g_seg_sum[(n * SSEG + j) * PCQ + q];
                float4 c = g_seg_cnt[(n * SSEG + j) * PCQ + q];
                ps.x += a.x; ps.y += a.y; ps.z += a.z; ps.w += a.w;
                pc.x += c.x; pc.y += c.y; pc.z += c.z; pc.w += c.w;
            }
        }
        #pragma unroll
        for (int k = 0; k < NSUB - 1; k++) {
            if (k < p) {
                float4 a = g_sub_sum[((n * SSEG + s) * NSUB + k) * PCQ + q];
                float4 c = g_sub_cnt[((n * SSEG + s) * NSUB + k) * PCQ + q];
                ps.x += a.x; ps.y += a.y; ps.z += a.z; ps.w += a.w;
                pc.x += c.x; pc.y += c.y; pc.z += c.z; pc.w += c.w;
            }
        }

        const int row0 = s * SEGL + SUBL * p;
        const float4* base = ts4 + ((size_t)(n * PL + row0)) * PCQ + q;
        float4* ob = out4 + ((size_t)(n * PL + row0)) * PCOQ + q;

        float4 rs = ps, rc = pc;
        #pragma unroll 8
        for (int i = 0; i < SUBL; i++) {
            float4 v = __ldcs(&base[(size_t)i * PCQ]);
            rs.x += v.x; rc.x += (v.x != 0.f) ? 1.f : 0.f;
            rs.y += v.y; rc.y += (v.y != 0.f) ? 1.f : 0.f;
            rs.z += v.z; rc.z += (v.z != 0.f) ? 1.f : 0.f;
            rs.w += v.w; rc.w += (v.w != 0.f) ? 1.f : 0.f;
            float4 o;
            o.x = fmaxf(__fdividef(rs.x, fmaxf(rc.x, 1.f)), 0.f);
            o.y = fmaxf(__fdividef(rs.y, fmaxf(rc.y, 1.f)), 0.f);
            o.z = fmaxf(__fdividef(rs.z, fmaxf(rc.z, 1.f)), 0.f);
            o.w = fmaxf(__fdividef(rs.w, fmaxf(rc.w, 1.f)), 0.f);
            __stcs(&ob[(size_t)i * PCOQ], o);
        }
    }
}

// ---------------------------------------------------------------------------
// kernel_launch: 5 pipelined launches; emit of phase i overlaps agg of i+1.
// Graph-capturable, allocation-free, deterministic (no flags, no spins).
// Inputs (metadata order): timesteps(64,2048,256) f32, dem(64,10) f32,
//   W1(10,40) f32, b1(40) f32, W2(40,20) f32, b2(20) f32.
// Output: (64,2048,276) f32.
// ---------------------------------------------------------------------------
extern "C" void kernel_launch(void* const* d_in, const int* in_sizes, int n_in,
                              void* d_out, int out_size) {
    const float* ts  = (const float*)d_in[0];
    const float* dem = (const float*)d_in[1];
    const float* W1  = (const float*)d_in[2];
    const float* b1  = (const float*)d_in[3];
    const float* W2  = (const float*)d_in[4];
    const float* b2  = (const float*)d_in[5];
    float* out = (float*)d_out;

    dim3 grid(2 * PSEG, PN);
    const float4* ts4 = (const float4*)ts;
    float4* out4 = (float4*)out;
    const int NPH = SSEG / PSEG;   // 4 phases
    for (int k = 0; k <= NPH; k++) {
        int agg_ph  = (k < NPH) ? k : -1;
        int emit_ph = k - 1;
        pipe_kernel<<<grid, 256>>>(ts4, dem, W1, b1, W2, b2, out4,
                                   agg_ph, emit_ph);
    }
}

// round 14
// speedup vs baseline: 1.0662x; 1.0662x over previous
#include <cuda_runtime.h>
#include <cuda_bf16.h>
#include <cstdint>

// Problem constants (fixed by the reference)
#define PN   64      // batch
#define PL   2048    // sequence length
#define PC   256     // timestep channels
#define PCQ  (PC / 4)       // 64 channel-quads
#define PDEM 10
#define PCO  276     // output channels = 256 + 20
#define PCOQ (PCO / 4)      // 69 output quads
#define SSEG 16      // segments along L
#define SEGL (PL / SSEG)    // 128
#define SUBL 32      // sub-segment rows (one row-phase)
#define NSUB 4       // sub-segments per segment

// Scratch (allocation-free __device__ globals, float4-aligned)
__device__ float4 g_sub_sum[PN * SSEG * NSUB * PCQ];  // [n][s*4+p][q]
__device__ float4 g_sub_cnt[PN * SSEG * NSUB * PCQ];
__device__ float4 g_seg_sum[PN * SSEG * PCQ];         // [n][s][q]
__device__ float4 g_seg_cnt[PN * SSEG * PCQ];

// ---------------------------------------------------------------------------
// Kernel 1: aggregates + dem MLP + dem-column output.
// Grid (SSEG, PN), 256 threads. Thread t: quad q = t&63, phase p = t>>6
// handles rows [32p, 32p+32), L2-allocating loads (__ldcg) keep the input
// resident in the 126 MB LTS for the emit kernel. Dem-column output uses
// write-through stores so it does not evict the input.
// ---------------------------------------------------------------------------
__global__ void __launch_bounds__(256)
agg_kernel(const float4* __restrict__ ts4,
           const float* __restrict__ dem,
           const float* __restrict__ W1,
           const float* __restrict__ b1,
           const float* __restrict__ W2,
           const float* __restrict__ b2,
           float4* __restrict__ out4) {
    const int s = blockIdx.x, n = blockIdx.y, t = threadIdx.x;
    const int p = t >> 6, q = t & 63;

    __shared__ float  s_sum[NSUB][PC];
    __shared__ float  s_cnt[NSUB][PC];
    __shared__ float  s_h[40];
    __shared__ float4 s_dem4[5];   // 20 dem channels as 5 float4

    const float4* base = ts4 + ((size_t)(n * PL + s * SEGL + SUBL * p)) * PCQ + q;

    // Aggregate 32 rows (L2-allocating loads)
    float4 a = make_float4(0.f, 0.f, 0.f, 0.f);
    float4 c = make_float4(0.f, 0.f, 0.f, 0.f);
    #pragma unroll 8
    for (int i = 0; i < SUBL; i++) {
        float4 v = __ldcg(&base[(size_t)i * PCQ]);
        a.x += v.x; a.y += v.y; a.z += v.z; a.w += v.w;
        c.x += (v.x != 0.f) ? 1.f : 0.f;
        c.y += (v.y != 0.f) ? 1.f : 0.f;
        c.z += (v.z != 0.f) ? 1.f : 0.f;
        c.w += (v.w != 0.f) ? 1.f : 0.f;
    }

    // Sub-aggregate (float4, coalesced)
    const int sub_idx = ((n * SSEG + s) * NSUB + p) * PCQ + q;
    g_sub_sum[sub_idx] = a;
    g_sub_cnt[sub_idx] = c;

    // dem MLP layer 1 (threads 0..39)
    if (t < 40) {
        float acc = b1[t];
        #pragma unroll
        for (int k = 0; k < PDEM; k++)
            acc = fmaf(dem[n * PDEM + k], W1[k * 40 + t], acc);
        s_h[t] = fmaxf(acc, 0.0f);
    }

    // Cross-phase reduce for the segment aggregate
    s_sum[p][4 * q + 0] = a.x; s_sum[p][4 * q + 1] = a.y;
    s_sum[p][4 * q + 2] = a.z; s_sum[p][4 * q + 3] = a.w;
    s_cnt[p][4 * q + 0] = c.x; s_cnt[p][4 * q + 1] = c.y;
    s_cnt[p][4 * q + 2] = c.z; s_cnt[p][4 * q + 3] = c.w;
    __syncthreads();

    // dem MLP layer 2 (threads 0..19); relu(const>=0)=const along L
    if (t < 20) {
        float acc = b2[t];
        #pragma unroll
        for (int k = 0; k < 40; k++) acc = fmaf(s_h[k], W2[k * 20 + t], acc);
        ((float*)s_dem4)[t] = fmaxf(acc, 0.0f);
    }

    float S = ((s_sum[0][t] + s_sum[1][t]) + s_sum[2][t]) + s_sum[3][t];
    float C = ((s_cnt[0][t] + s_cnt[1][t]) + s_cnt[2][t]) + s_cnt[3][t];
    const int seg_base = (n * SSEG + s) * PCQ;
    ((float*)&g_seg_sum[seg_base])[t] = S;
    ((float*)&g_seg_cnt[seg_base])[t] = C;
    __syncthreads();   // s_dem4 ready

    // dem-column output, write-through (no L2 allocation)
    float4* obseg = out4 + ((size_t)(n * PL + s * SEGL)) * PCOQ;
    #pragma unroll
    for (int j = t; j < SEGL * 5; j += 256) {
        int row = j / 5;
        int cc  = j - row * 5;
        __stwt(&obseg[(size_t)row * PCOQ + PCQ + cc], s_dem4[cc]);
    }
}

// ---------------------------------------------------------------------------
// Kernel 2: emit — sync-free, smem-free pure stream.
// Grid (SSEG, PN), 256 threads. Thread t: quad q = t&63, phase p = t>>6.
// Two-level lookback (L2-hot aggregates), then scan 32 rows:
// LDG.128 (L2-hit expected) -> FADDs -> MUFU rcp -> STG.128 WRITE-THROUGH
// (st.global.wt: output does not evict the still-unread input from L2).
// ---------------------------------------------------------------------------
__global__ void __launch_bounds__(256)
emit_kernel(const float4* __restrict__ ts4, float4* __restrict__ out4) {
    const int s = blockIdx.x, n = blockIdx.y, t = threadIdx.x;
    const int p = t >> 6, q = t & 63;

    // Two-level lookback
    float4 ps = make_float4(0.f, 0.f, 0.f, 0.f);
    float4 pc = make_float4(0.f, 0.f, 0.f, 0.f);
    #pragma unroll
    for (int j = 0; j < SSEG - 1; j++) {
        if (j < s) {
            float4 a = g_seg_sum[(n * SSEG + j) * PCQ + q];
            float4 c = g_seg_cnt[(n * SSEG + j) * PCQ + q];
            ps.x += a.x; ps.y += a.y; ps.z += a.z; ps.w += a.w;
            pc.x += c.x; pc.y += c.y; pc.z += c.z; pc.w += c.w;
        }
    }
    #pragma unroll
    for (int k = 0; k < NSUB - 1; k++) {
        if (k < p) {
            float4 a = g_sub_sum[((n * SSEG + s) * NSUB + k) * PCQ + q];
            float4 c = g_sub_cnt[((n * SSEG + s) * NSUB + k) * PCQ + q];
            ps.x += a.x; ps.y += a.y; ps.z += a.z; ps.w += a.w;
            pc.x += c.x; pc.y += c.y; pc.z += c.z; pc.w += c.w;
        }
    }

    // Scan this phase's 32 rows
    const int row0 = s * SEGL + SUBL * p;
    const float4* base = ts4 + ((size_t)(n * PL + row0)) * PCQ + q;
    float4* ob = out4 + ((size_t)(n * PL + row0)) * PCOQ + q;

    float4 rs = ps, rc = pc;
    #pragma unroll 8
    for (int i = 0; i < SUBL; i++) {
        float4 v = __ldcs(&base[(size_t)i * PCQ]);
        rs.x += v.x; rc.x += (v.x != 0.f) ? 1.f : 0.f;
        rs.y += v.y; rc.y += (v.y != 0.f) ? 1.f : 0.f;
        rs.z += v.z; rc.z += (v.z != 0.f) ? 1.f : 0.f;
        rs.w += v.w; rc.w += (v.w != 0.f) ? 1.f : 0.f;
        float4 o;
        o.x = fmaxf(__fdividef(rs.x, fmaxf(rc.x, 1.f)), 0.f);
        o.y = fmaxf(__fdividef(rs.y, fmaxf(rc.y, 1.f)), 0.f);
        o.z = fmaxf(__fdividef(rs.z, fmaxf(rc.z, 1.f)), 0.f);
        o.w = fmaxf(__fdividef(rs.w, fmaxf(rc.w, 1.f)), 0.f);
        __stwt(&ob[(size_t)i * PCOQ], o);
    }
}

// ---------------------------------------------------------------------------
// kernel_launch: aggregate(+dem) then emit; kernel boundary is the only sync.
// Graph-capturable, allocation-free, deterministic (no flags, no spins).
// Inputs (metadata order): timesteps(64,2048,256) f32, dem(64,10) f32,
//   W1(10,40) f32, b1(40) f32, W2(40,20) f32, b2(20) f32.
// Output: (64,2048,276) f32.
// ---------------------------------------------------------------------------
extern "C" void kernel_launch(void* const* d_in, const int* in_sizes, int n_in,
                              void* d_out, int out_size) {
    const float* ts  = (const float*)d_in[0];
    const float* dem = (const float*)d_in[1];
    const float* W1  = (const float*)d_in[2];
    const float* b1  = (const float*)d_in[3];
    const float* W2  = (const float*)d_in[4];
    const float* b2  = (const float*)d_in[5];
    float* out = (float*)d_out;

    dim3 grid(SSEG, PN);
    agg_kernel<<<grid, 256>>>((const float4*)ts, dem, W1, b1, W2, b2,
                              (float4*)out);
    emit_kernel<<<grid, 256>>>((const float4*)ts, (float4*)out);
}

// round 15
// speedup vs baseline: 1.2468x; 1.1694x over previous
#include <cuda_runtime.h>
#include <cuda_bf16.h>
#include <cstdint>

// Problem constants (fixed by the reference)
#define PN   64      // batch
#define PL   2048    // sequence length
#define PC   256     // timestep channels
#define PCQ  (PC / 4)       // 64 channel-quads
#define PDEM 10
#define PCO  276     // output channels = 256 + 20
#define PCOQ (PCO / 4)      // 69 output quads
#define SSEG 16      // segments along L
#define SEGL (PL / SSEG)    // 128
#define SUBL 16      // sub-segment rows (one row-phase)
#define NSUB 8       // sub-segments per segment
#define NTHR 512     // threads per block (64 quads x 8 phases)

// Scratch (allocation-free __device__ globals, float4-aligned)
__device__ float4 g_sub_sum[PN * SSEG * NSUB * PCQ];  // [n][s*8+p][q]
__device__ float4 g_sub_cnt[PN * SSEG * NSUB * PCQ];
__device__ float4 g_seg_sum[PN * SSEG * PCQ];         // [n][s][q]
__device__ float4 g_seg_cnt[PN * SSEG * PCQ];

// ---------------------------------------------------------------------------
// Kernel 1: aggregates + dem MLP + dem-column output.
// Grid (SSEG, PN), 512 threads. Thread t: quad q = t&63, phase p = t>>6
// aggregates rows [16p, 16p+16) of its segment (L2-allocating loads keep the
// input resident for emit). Writes sub- and segment aggregates; computes the
// dem MLP; writes the 20 constant dem output channels (relu(c>=0)=c).
// ---------------------------------------------------------------------------
__global__ void __launch_bounds__(NTHR)
agg_kernel(const float4* __restrict__ ts4,
           const float* __restrict__ dem,
           const float* __restrict__ W1,
           const float* __restrict__ b1,
           const float* __restrict__ W2,
           const float* __restrict__ b2,
           float4* __restrict__ out4) {
    const int s = blockIdx.x, n = blockIdx.y, t = threadIdx.x;
    const int p = t >> 6, q = t & 63;

    __shared__ float  s_sum[NSUB][PC];   // 8 KB
    __shared__ float  s_cnt[NSUB][PC];   // 8 KB
    __shared__ float  s_h[40];
    __shared__ float4 s_dem4[5];         // 20 dem channels as 5 float4

    const float4* base = ts4 + ((size_t)(n * PL + s * SEGL + SUBL * p)) * PCQ + q;

    // Aggregate 16 rows (L2-allocating loads)
    float4 a = make_float4(0.f, 0.f, 0.f, 0.f);
    float4 c = make_float4(0.f, 0.f, 0.f, 0.f);
    #pragma unroll
    for (int i = 0; i < SUBL; i++) {
        float4 v = __ldcg(&base[(size_t)i * PCQ]);
        a.x += v.x; a.y += v.y; a.z += v.z; a.w += v.w;
        c.x += (v.x != 0.f) ? 1.f : 0.f;
        c.y += (v.y != 0.f) ? 1.f : 0.f;
        c.z += (v.z != 0.f) ? 1.f : 0.f;
        c.w += (v.w != 0.f) ? 1.f : 0.f;
    }

    // Sub-aggregate (float4, coalesced)
    const int sub_idx = ((n * SSEG + s) * NSUB + p) * PCQ + q;
    g_sub_sum[sub_idx] = a;
    g_sub_cnt[sub_idx] = c;

    // dem MLP layer 1 (threads 0..39)
    if (t < 40) {
        float acc = b1[t];
        #pragma unroll
        for (int k = 0; k < PDEM; k++)
            acc = fmaf(dem[n * PDEM + k], W1[k * 40 + t], acc);
        s_h[t] = fmaxf(acc, 0.0f);
    }

    // Cross-phase reduce for the segment aggregate
    s_sum[p][4 * q + 0] = a.x; s_sum[p][4 * q + 1] = a.y;
    s_sum[p][4 * q + 2] = a.z; s_sum[p][4 * q + 3] = a.w;
    s_cnt[p][4 * q + 0] = c.x; s_cnt[p][4 * q + 1] = c.y;
    s_cnt[p][4 * q + 2] = c.z; s_cnt[p][4 * q + 3] = c.w;
    __syncthreads();

    // dem MLP layer 2 (threads 0..19)
    if (t < 20) {
        float acc = b2[t];
        #pragma unroll
        for (int k = 0; k < 40; k++) acc = fmaf(s_h[k], W2[k * 20 + t], acc);
        ((float*)s_dem4)[t] = fmaxf(acc, 0.0f);
    }

    if (t < PC) {
        float S = 0.f, C = 0.f;
        #pragma unroll
        for (int pp = 0; pp < NSUB; pp++) { S += s_sum[pp][t]; C += s_cnt[pp][t]; }
        const int seg_base = (n * SSEG + s) * PCQ;
        ((float*)&g_seg_sum[seg_base])[t] = S;
        ((float*)&g_seg_cnt[seg_base])[t] = C;
    }
    __syncthreads();   // s_dem4 ready

    // dem-column output for this segment's 128 rows (5 float4 per row)
    float4* obseg = out4 + ((size_t)(n * PL + s * SEGL)) * PCOQ;
    #pragma unroll
    for (int j = t; j < SEGL * 5; j += NTHR) {
        int row = j / 5;
        int cc  = j - row * 5;
        __stcs(&obseg[(size_t)row * PCOQ + PCQ + cc], s_dem4[cc]);
    }
}

// ---------------------------------------------------------------------------
// Kernel 2: emit — sync-free, smem-free stream with prefetch double-buffer.
// Grid (SSEG, PN), 512 threads. Thread t: quad q = t&63, phase p = t>>6 owns
// rows [16p, 16p+16). Two-level lookback (<=15 seg + <=7 sub, L2-hot), then
// a 16-iteration scan: prefetched LDG.128 -> FADDs -> MUFU rcp -> STG.128.
// ---------------------------------------------------------------------------
__global__ void __launch_bounds__(NTHR)
emit_kernel(const float4* __restrict__ ts4, float4* __restrict__ out4) {
    const int s = blockIdx.x, n = blockIdx.y, t = threadIdx.x;
    const int p = t >> 6, q = t & 63;

    // Two-level lookback
    float4 ps = make_float4(0.f, 0.f, 0.f, 0.f);
    float4 pc = make_float4(0.f, 0.f, 0.f, 0.f);
    #pragma unroll
    for (int j = 0; j < SSEG - 1; j++) {
        if (j < s) {
            float4 a = g_seg_sum[(n * SSEG + j) * PCQ + q];
            float4 c = g_seg_cnt[(n * SSEG + j) * PCQ + q];
            ps.x += a.x; ps.y += a.y; ps.z += a.z; ps.w += a.w;
            pc.x += c.x; pc.y += c.y; pc.z += c.z; pc.w += c.w;
        }
    }
    #pragma unroll
    for (int k = 0; k < NSUB - 1; k++) {
        if (k < p) {
            float4 a = g_sub_sum[((n * SSEG + s) * NSUB + k) * PCQ + q];
            float4 c = g_sub_cnt[((n * SSEG + s) * NSUB + k) * PCQ + q];
            ps.x += a.x; ps.y += a.y; ps.z += a.z; ps.w += a.w;
            pc.x += c.x; pc.y += c.y; pc.z += c.z; pc.w += c.w;
        }
    }

    // Scan this phase's 16 rows with a one-deep prefetch pipeline
    const int row0 = s * SEGL + SUBL * p;
    const float4* base = ts4 + ((size_t)(n * PL + row0)) * PCQ + q;
    float4* ob = out4 + ((size_t)(n * PL + row0)) * PCOQ + q;

    float4 rs = ps, rc = pc;
    float4 v = __ldcs(&base[0]);
    #pragma unroll
    for (int i = 0; i < SUBL; i++) {
        float4 vn;
        if (i + 1 < SUBL) vn = __ldcs(&base[(size_t)(i + 1) * PCQ]);
        rs.x += v.x; rc.x += (v.x != 0.f) ? 1.f : 0.f;
        rs.y += v.y; rc.y += (v.y != 0.f) ? 1.f : 0.f;
        rs.z += v.z; rc.z += (v.z != 0.f) ? 1.f : 0.f;
        rs.w += v.w; rc.w += (v.w != 0.f) ? 1.f : 0.f;
        float4 o;
        o.x = fmaxf(__fdividef(rs.x, fmaxf(rc.x, 1.f)), 0.f);
        o.y = fmaxf(__fdividef(rs.y, fmaxf(rc.y, 1.f)), 0.f);
        o.z = fmaxf(__fdividef(rs.z, fmaxf(rc.z, 1.f)), 0.f);
        o.w = fmaxf(__fdividef(rs.w, fmaxf(rc.w, 1.f)), 0.f);
        __stcs(&ob[(size_t)i * PCOQ], o);
        v = vn;
    }
}

// ---------------------------------------------------------------------------
// kernel_launch: aggregate(+dem) then emit; kernel boundary is the only sync.
// Graph-capturable, allocation-free, deterministic (no flags, no spins).
// Inputs (metadata order): timesteps(64,2048,256) f32, dem(64,10) f32,
//   W1(10,40) f32, b1(40) f32, W2(40,20) f32, b2(20) f32.
// Output: (64,2048,276) f32.
// ---------------------------------------------------------------------------
extern "C" void kernel_launch(void* const* d_in, const int* in_sizes, int n_in,
                              void* d_out, int out_size) {
    const float* ts  = (const float*)d_in[0];
    const float* dem = (const float*)d_in[1];
    const float* W1  = (const float*)d_in[2];
    const float* b1  = (const float*)d_in[3];
    const float* W2  = (const float*)d_in[4];
    const float* b2  = (const float*)d_in[5];
    float* out = (float*)d_out;

    dim3 grid(SSEG, PN);
    agg_kernel<<<grid, NTHR>>>((const float4*)ts, dem, W1, b1, W2, b2,
                               (float4*)out);
    emit_kernel<<<grid, NTHR>>>((const float4*)ts, (float4*)out);
}

// round 16
// speedup vs baseline: 1.2941x; 1.0379x over previous
#include <cuda_runtime.h>
#include <cuda_bf16.h>
#include <cstdint>

// Problem constants (fixed by the reference)
#define PN   64      // batch
#define PL   2048    // sequence length
#define PC   256     // timestep channels
#define PCQ  (PC / 4)       // 64 channel-quads
#define PDEM 10
#define PCO  276     // output channels = 256 + 20
#define PCOQ (PCO / 4)      // 69 output quads
#define SSEG 16      // segments along L
#define SEGL (PL / SSEG)    // 128
#define SUBL 16      // sub-segment rows (one row-phase)
#define NSUB 8       // sub-segments per segment
#define NTHR 512     // threads per block (64 quads x 8 phases)
#define BAT  8       // rows per register batch in emit

// Scratch (allocation-free __device__ globals, float4-aligned)
__device__ float4 g_sub_sum[PN * SSEG * NSUB * PCQ];  // [n][s*8+p][q]
__device__ float4 g_sub_cnt[PN * SSEG * NSUB * PCQ];
__device__ float4 g_seg_sum[PN * SSEG * PCQ];         // [n][s][q]
__device__ float4 g_seg_cnt[PN * SSEG * PCQ];

// ---------------------------------------------------------------------------
// Kernel 1: aggregates + dem MLP + dem-column output.
// Grid (SSEG, PN), 512 threads. Thread t: quad q = t&63, phase p = t>>6
// aggregates rows [16p, 16p+16) of its segment (L2-allocating loads keep the
// input resident for emit). Writes sub- and segment aggregates; computes the
// dem MLP; writes the 20 constant dem output channels (relu(c>=0)=c).
// ---------------------------------------------------------------------------
__global__ void __launch_bounds__(NTHR)
agg_kernel(const float4* __restrict__ ts4,
           const float* __restrict__ dem,
           const float* __restrict__ W1,
           const float* __restrict__ b1,
           const float* __restrict__ W2,
           const float* __restrict__ b2,
           float4* __restrict__ out4) {
    const int s = blockIdx.x, n = blockIdx.y, t = threadIdx.x;
    const int p = t >> 6, q = t & 63;

    __shared__ float  s_sum[NSUB][PC];   // 8 KB
    __shared__ float  s_cnt[NSUB][PC];   // 8 KB
    __shared__ float  s_h[40];
    __shared__ float4 s_dem4[5];         // 20 dem channels as 5 float4

    const float4* base = ts4 + ((size_t)(n * PL + s * SEGL + SUBL * p)) * PCQ + q;

    // Aggregate 16 rows (L2-allocating loads)
    float4 a = make_float4(0.f, 0.f, 0.f, 0.f);
    float4 c = make_float4(0.f, 0.f, 0.f, 0.f);
    #pragma unroll
    for (int i = 0; i < SUBL; i++) {
        float4 v = __ldcg(&base[(size_t)i * PCQ]);
        a.x += v.x; a.y += v.y; a.z += v.z; a.w += v.w;
        c.x += (v.x != 0.f) ? 1.f : 0.f;
        c.y += (v.y != 0.f) ? 1.f : 0.f;
        c.z += (v.z != 0.f) ? 1.f : 0.f;
        c.w += (v.w != 0.f) ? 1.f : 0.f;
    }

    // Sub-aggregate (float4, coalesced)
    const int sub_idx = ((n * SSEG + s) * NSUB + p) * PCQ + q;
    g_sub_sum[sub_idx] = a;
    g_sub_cnt[sub_idx] = c;

    // dem MLP layer 1 (threads 0..39)
    if (t < 40) {
        float acc = b1[t];
        #pragma unroll
        for (int k = 0; k < PDEM; k++)
            acc = fmaf(dem[n * PDEM + k], W1[k * 40 + t], acc);
        s_h[t] = fmaxf(acc, 0.0f);
    }

    // Cross-phase reduce for the segment aggregate
    s_sum[p][4 * q + 0] = a.x; s_sum[p][4 * q + 1] = a.y;
    s_sum[p][4 * q + 2] = a.z; s_sum[p][4 * q + 3] = a.w;
    s_cnt[p][4 * q + 0] = c.x; s_cnt[p][4 * q + 1] = c.y;
    s_cnt[p][4 * q + 2] = c.z; s_cnt[p][4 * q + 3] = c.w;
    __syncthreads();

    // dem MLP layer 2 (threads 0..19)
    if (t < 20) {
        float acc = b2[t];
        #pragma unroll
        for (int k = 0; k < 40; k++) acc = fmaf(s_h[k], W2[k * 20 + t], acc);
        ((float*)s_dem4)[t] = fmaxf(acc, 0.0f);
    }

    if (t < PC) {
        float S = 0.f, C = 0.f;
        #pragma unroll
        for (int pp = 0; pp < NSUB; pp++) { S += s_sum[pp][t]; C += s_cnt[pp][t]; }
        const int seg_base = (n * SSEG + s) * PCQ;
        ((float*)&g_seg_sum[seg_base])[t] = S;
        ((float*)&g_seg_cnt[seg_base])[t] = C;
    }
    __syncthreads();   // s_dem4 ready

    // dem-column output for this segment's 128 rows (5 float4 per row)
    float4* obseg = out4 + ((size_t)(n * PL + s * SEGL)) * PCOQ;
    #pragma unroll
    for (int j = t; j < SEGL * 5; j += NTHR) {
        int row = j / 5;
        int cc  = j - row * 5;
        __stcs(&obseg[(size_t)row * PCOQ + PCQ + cc], s_dem4[cc]);
    }
}

// ---------------------------------------------------------------------------
// Kernel 2: emit — sync-free, smem-free, batch-loaded scan (MLP = 8).
// Grid (SSEG, PN), 512 threads. Thread t: quad q = t&63, phase p = t>>6 owns
// rows [16p, 16p+16). Two-level lookback (<=15 seg + <=7 sub, L2-hot), then
// two register batches of 8 rows: 8 back-to-back LDG.128 (one scoreboard
// wait per batch), then the dependent FADD/MUFU/STG.128 chain per row.
// ---------------------------------------------------------------------------
__global__ void __launch_bounds__(NTHR)
emit_kernel(const float4* __restrict__ ts4, float4* __restrict__ out4) {
    const int s = blockIdx.x, n = blockIdx.y, t = threadIdx.x;
    const int p = t >> 6, q = t & 63;

    // Two-level lookback
    float4 ps = make_float4(0.f, 0.f, 0.f, 0.f);
    float4 pc = make_float4(0.f, 0.f, 0.f, 0.f);
    #pragma unroll
    for (int j = 0; j < SSEG - 1; j++) {
        if (j < s) {
            float4 a = g_seg_sum[(n * SSEG + j) * PCQ + q];
            float4 c = g_seg_cnt[(n * SSEG + j) * PCQ + q];
            ps.x += a.x; ps.y += a.y; ps.z += a.z; ps.w += a.w;
            pc.x += c.x; pc.y += c.y; pc.z += c.z; pc.w += c.w;
        }
    }
    #pragma unroll
    for (int k = 0; k < NSUB - 1; k++) {
        if (k < p) {
            float4 a = g_sub_sum[((n * SSEG + s) * NSUB + k) * PCQ + q];
            float4 c = g_sub_cnt[((n * SSEG + s) * NSUB + k) * PCQ + q];
            ps.x += a.x; ps.y += a.y; ps.z += a.z; ps.w += a.w;
            pc.x += c.x; pc.y += c.y; pc.z += c.z; pc.w += c.w;
        }
    }

    const int row0 = s * SEGL + SUBL * p;
    const float4* base = ts4 + ((size_t)(n * PL + row0)) * PCQ + q;
    float4* ob = out4 + ((size_t)(n * PL + row0)) * PCOQ + q;

    float4 rs = ps, rc = pc;
    float4 buf[BAT];

    #pragma unroll
    for (int b = 0; b < SUBL / BAT; b++) {
        // Batch load: 8 independent LDG.128, issued back-to-back
        #pragma unroll
        for (int i = 0; i < BAT; i++)
            buf[i] = __ldcs(&base[(size_t)(b * BAT + i) * PCQ]);
        // Dependent scan + store over the buffered rows
        #pragma unroll
        for (int i = 0; i < BAT; i++) {
            float4 v = buf[i];
            rs.x += v.x; rc.x += (v.x != 0.f) ? 1.f : 0.f;
            rs.y += v.y; rc.y += (v.y != 0.f) ? 1.f : 0.f;
            rs.z += v.z; rc.z += (v.z != 0.f) ? 1.f : 0.f;
            rs.w += v.w; rc.w += (v.w != 0.f) ? 1.f : 0.f;
            float4 o;
            o.x = fmaxf(__fdividef(rs.x, fmaxf(rc.x, 1.f)), 0.f);
            o.y = fmaxf(__fdividef(rs.y, fmaxf(rc.y, 1.f)), 0.f);
            o.z = fmaxf(__fdividef(rs.z, fmaxf(rc.z, 1.f)), 0.f);
            o.w = fmaxf(__fdividef(rs.w, fmaxf(rc.w, 1.f)), 0.f);
            __stcs(&ob[(size_t)(b * BAT + i) * PCOQ], o);
        }
    }
}

// ---------------------------------------------------------------------------
// kernel_launch: aggregate(+dem) then emit; kernel boundary is the only sync.
// Graph-capturable, allocation-free, deterministic (no flags, no spins).
// Inputs (metadata order): timesteps(64,2048,256) f32, dem(64,10) f32,
//   W1(10,40) f32, b1(40) f32, W2(40,20) f32, b2(20) f32.
// Output: (64,2048,276) f32.
// ---------------------------------------------------------------------------
extern "C" void kernel_launch(void* const* d_in, const int* in_sizes, int n_in,
                              void* d_out, int out_size) {
    const float* ts  = (const float*)d_in[0];
    const float* dem = (const float*)d_in[1];
    const float* W1  = (const float*)d_in[2];
    const float* b1  = (const float*)d_in[3];
    const float* W2  = (const float*)d_in[4];
    const float* b2  = (const float*)d_in[5];
    float* out = (float*)d_out;

    dim3 grid(SSEG, PN);
    agg_kernel<<<grid, NTHR>>>((const float4*)ts, dem, W1, b1, W2, b2,
                               (float4*)out);
    emit_kernel<<<grid, NTHR>>>((const float4*)ts, (float4*)out);
}

// round 17
// speedup vs baseline: 1.3335x; 1.0305x over previous
#include <cuda_runtime.h>
#include <cuda_bf16.h>
#include <cstdint>

// Problem constants (fixed by the reference)
#define PN   64      // batch
#define PL   2048    // sequence length
#define PC   256     // timestep channels
#define PCQ  (PC / 4)       // 64 channel-quads
#define PDEM 10
#define PCO  276     // output channels = 256 + 20
#define PCOQ (PCO / 4)      // 69 output quads
#define SSEG 16      // segments along L
#define SEGL (PL / SSEG)    // 128
#define SUBL 16      // sub-segment rows (one row-phase)
#define NSUB 8       // sub-segments per segment
#define NTHR 512     // threads per block (64 quads x 8 phases)
#define BAT  8       // rows per register batch in emit
#define NTILE (SSEG * PN)   // 1024 tiles

// Scratch (allocation-free __device__ globals, float4-aligned)
__device__ float4 g_sub_sum[PN * SSEG * NSUB * PCQ];  // [n][s*8+p][q]
__device__ float4 g_sub_cnt[PN * SSEG * NSUB * PCQ];
__device__ float4 g_seg_sum[PN * SSEG * PCQ];         // [n][s][q]
__device__ float4 g_seg_cnt[PN * SSEG * PCQ];

// ---------------------------------------------------------------------------
// Kernel 1: aggregates + dem MLP + dem-column output.
// Grid (SSEG, PN), 512 threads. Thread t: quad q = t&63, phase p = t>>6
// aggregates rows [16p, 16p+16) of its segment (L2-allocating loads keep the
// input resident for emit). Writes sub- and segment aggregates; computes the
// dem MLP; writes the 20 constant dem output channels (relu(c>=0)=c).
// ---------------------------------------------------------------------------
__global__ void __launch_bounds__(NTHR)
agg_kernel(const float4* __restrict__ ts4,
           const float* __restrict__ dem,
           const float* __restrict__ W1,
           const float* __restrict__ b1,
           const float* __restrict__ W2,
           const float* __restrict__ b2,
           float4* __restrict__ out4) {
    const int s = blockIdx.x, n = blockIdx.y, t = threadIdx.x;
    const int p = t >> 6, q = t & 63;

    __shared__ float  s_sum[NSUB][PC];   // 8 KB
    __shared__ float  s_cnt[NSUB][PC];   // 8 KB
    __shared__ float  s_h[40];
    __shared__ float4 s_dem4[5];         // 20 dem channels as 5 float4

    const float4* base = ts4 + ((size_t)(n * PL + s * SEGL + SUBL * p)) * PCQ + q;

    // Aggregate 16 rows (L2-allocating loads)
    float4 a = make_float4(0.f, 0.f, 0.f, 0.f);
    float4 c = make_float4(0.f, 0.f, 0.f, 0.f);
    #pragma unroll
    for (int i = 0; i < SUBL; i++) {
        float4 v = __ldcg(&base[(size_t)i * PCQ]);
        a.x += v.x; a.y += v.y; a.z += v.z; a.w += v.w;
        c.x += (v.x != 0.f) ? 1.f : 0.f;
        c.y += (v.y != 0.f) ? 1.f : 0.f;
        c.z += (v.z != 0.f) ? 1.f : 0.f;
        c.w += (v.w != 0.f) ? 1.f : 0.f;
    }

    // Sub-aggregate (float4, coalesced)
    const int sub_idx = ((n * SSEG + s) * NSUB + p) * PCQ + q;
    g_sub_sum[sub_idx] = a;
    g_sub_cnt[sub_idx] = c;

    // dem MLP layer 1 (threads 0..39)
    if (t < 40) {
        float acc = b1[t];
        #pragma unroll
        for (int k = 0; k < PDEM; k++)
            acc = fmaf(dem[n * PDEM + k], W1[k * 40 + t], acc);
        s_h[t] = fmaxf(acc, 0.0f);
    }

    // Cross-phase reduce for the segment aggregate
    s_sum[p][4 * q + 0] = a.x; s_sum[p][4 * q + 1] = a.y;
    s_sum[p][4 * q + 2] = a.z; s_sum[p][4 * q + 3] = a.w;
    s_cnt[p][4 * q + 0] = c.x; s_cnt[p][4 * q + 1] = c.y;
    s_cnt[p][4 * q + 2] = c.z; s_cnt[p][4 * q + 3] = c.w;
    __syncthreads();

    // dem MLP layer 2 (threads 0..19)
    if (t < 20) {
        float acc = b2[t];
        #pragma unroll
        for (int k = 0; k < 40; k++) acc = fmaf(s_h[k], W2[k * 20 + t], acc);
        ((float*)s_dem4)[t] = fmaxf(acc, 0.0f);
    }

    if (t < PC) {
        float S = 0.f, C = 0.f;
        #pragma unroll
        for (int pp = 0; pp < NSUB; pp++) { S += s_sum[pp][t]; C += s_cnt[pp][t]; }
        const int seg_base = (n * SSEG + s) * PCQ;
        ((float*)&g_seg_sum[seg_base])[t] = S;
        ((float*)&g_seg_cnt[seg_base])[t] = C;
    }
    __syncthreads();   // s_dem4 ready

    // dem-column output for this segment's 128 rows (5 float4 per row)
    float4* obseg = out4 + ((size_t)(n * PL + s * SEGL)) * PCOQ;
    #pragma unroll
    for (int j = t; j < SEGL * 5; j += NTHR) {
        int row = j / 5;
        int cc  = j - row * 5;
        __stcs(&obseg[(size_t)row * PCOQ + PCQ + cc], s_dem4[cc]);
    }
}

// ---------------------------------------------------------------------------
// Kernel 2: emit — sync-free, smem-free, batch-loaded scan (MLP = 8),
// with REVERSED tile mapping: emit's first-executing blocks process the
// tiles agg wrote LAST (still L2-resident); later emit waves take the older
// tiles, minimizing L2 misses under recency-based replacement.
// Thread t: quad q = t&63, phase p = t>>6 owns rows [16p, 16p+16).
// ---------------------------------------------------------------------------
__global__ void __launch_bounds__(NTHR)
emit_kernel(const float4* __restrict__ ts4, float4* __restrict__ out4) {
    const int lin  = blockIdx.y * SSEG + blockIdx.x;
    const int rlin = (NTILE - 1) - lin;          // reversed tile index
    const int s = rlin & (SSEG - 1);
    const int n = rlin >> 4;                     // rlin / SSEG
    const int t = threadIdx.x;
    const int p = t >> 6, q = t & 63;

    // Two-level lookback
    float4 ps = make_float4(0.f, 0.f, 0.f, 0.f);
    float4 pc = make_float4(0.f, 0.f, 0.f, 0.f);
    #pragma unroll
    for (int j = 0; j < SSEG - 1; j++) {
        if (j < s) {
            float4 a = g_seg_sum[(n * SSEG + j) * PCQ + q];
            float4 c = g_seg_cnt[(n * SSEG + j) * PCQ + q];
            ps.x += a.x; ps.y += a.y; ps.z += a.z; ps.w += a.w;
            pc.x += c.x; pc.y += c.y; pc.z += c.z; pc.w += c.w;
        }
    }
    #pragma unroll
    for (int k = 0; k < NSUB - 1; k++) {
        if (k < p) {
            float4 a = g_sub_sum[((n * SSEG + s) * NSUB + k) * PCQ + q];
            float4 c = g_sub_cnt[((n * SSEG + s) * NSUB + k) * PCQ + q];
            ps.x += a.x; ps.y += a.y; ps.z += a.z; ps.w += a.w;
            pc.x += c.x; pc.y += c.y; pc.z += c.z; pc.w += c.w;
        }
    }

    const int row0 = s * SEGL + SUBL * p;
    const float4* base = ts4 + ((size_t)(n * PL + row0)) * PCQ + q;
    float4* ob = out4 + ((size_t)(n * PL + row0)) * PCOQ + q;

    float4 rs = ps, rc = pc;
    float4 buf[BAT];

    #pragma unroll
    for (int b = 0; b < SUBL / BAT; b++) {
        // Batch load: 8 independent LDG.128, issued back-to-back
        #pragma unroll
        for (int i = 0; i < BAT; i++)
            buf[i] = __ldcs(&base[(size_t)(b * BAT + i) * PCQ]);
        // Dependent scan + store over the buffered rows
        #pragma unroll
        for (int i = 0; i < BAT; i++) {
            float4 v = buf[i];
            rs.x += v.x; rc.x += (v.x != 0.f) ? 1.f : 0.f;
            rs.y += v.y; rc.y += (v.y != 0.f) ? 1.f : 0.f;
            rs.z += v.z; rc.z += (v.z != 0.f) ? 1.f : 0.f;
            rs.w += v.w; rc.w += (v.w != 0.f) ? 1.f : 0.f;
            float4 o;
            o.x = fmaxf(__fdividef(rs.x, fmaxf(rc.x, 1.f)), 0.f);
            o.y = fmaxf(__fdividef(rs.y, fmaxf(rc.y, 1.f)), 0.f);
            o.z = fmaxf(__fdividef(rs.z, fmaxf(rc.z, 1.f)), 0.f);
            o.w = fmaxf(__fdividef(rs.w, fmaxf(rc.w, 1.f)), 0.f);
            __stcs(&ob[(size_t)(b * BAT + i) * PCOQ], o);
        }
    }
}

// ---------------------------------------------------------------------------
// kernel_launch: aggregate(+dem) then emit; kernel boundary is the only sync.
// Graph-capturable, allocation-free, deterministic (no flags, no spins).
// Inputs (metadata order): timesteps(64,2048,256) f32, dem(64,10) f32,
//   W1(10,40) f32, b1(40) f32, W2(40,20) f32, b2(20) f32.
// Output: (64,2048,276) f32.
// ---------------------------------------------------------------------------
extern "C" void kernel_launch(void* const* d_in, const int* in_sizes, int n_in,
                              void* d_out, int out_size) {
    const float* ts  = (const float*)d_in[0];
    const float* dem = (const float*)d_in[1];
    const float* W1  = (const float*)d_in[2];
    const float* b1  = (const float*)d_in[3];
    const float* W2  = (const float*)d_in[4];
    const float* b2  = (const float*)d_in[5];
    float* out = (float*)d_out;

    dim3 grid(SSEG, PN);
    agg_kernel<<<grid, NTHR>>>((const float4*)ts, dem, W1, b1, W2, b2,
                               (float4*)out);
    emit_kernel<<<grid, NTHR>>>((const float4*)ts, (float4*)out);
}